// round 4
// baseline (speedup 1.0000x reference)
#include <cuda_runtime.h>
#include <cuda_bf16.h>

#define NN 512
#define NE (512*512)
#define NMASK (NN - 1)

// ---------------- scratch (static device globals; no allocation) ----------------
__device__ int    g_counts[NN];
__device__ int    g_offsets[NN + 1];
__device__ int    g_cursor[NN];
__device__ int    g_src[NE];
__device__ float4 g_ea[NE];
__device__ float  g_h1[NN * 36];
__device__ float  g_h2[NN * 24];
__device__ float  g_h3[NN * 8];

// packed f32x2 FMA (Blackwell sm_103a; see ptx_helpers.cuh style)
__device__ __forceinline__ float2 ffma2(float2 a, float2 b, float2 c) {
    unsigned long long ra, rb, rc, rd;
    memcpy(&ra, &a, 8); memcpy(&rb, &b, 8); memcpy(&rc, &c, 8);
    asm("fma.rn.f32x2 %0, %1, %2, %3;" : "=l"(rd) : "l"(ra), "l"(rb), "l"(rc));
    float2 d; memcpy(&d, &rd, 8);
    return d;
}

// ---------------- counting sort of edges by dst ----------------
__global__ void k_zero_counts() {
    int t = blockIdx.x * blockDim.x + threadIdx.x;
    if (t < NN) g_counts[t] = 0;
}

__global__ void k_hist(const int* __restrict__ ei) {
    __shared__ int sc[NN];
    for (int i = threadIdx.x; i < NN; i += blockDim.x) sc[i] = 0;
    __syncthreads();
    for (int e = blockIdx.x * blockDim.x + threadIdx.x; e < NE; e += gridDim.x * blockDim.x) {
        int d = ei[NE + e] & NMASK;
        atomicAdd(&sc[d], 1);
    }
    __syncthreads();
    for (int i = threadIdx.x; i < NN; i += blockDim.x) {
        int v = sc[i];
        if (v) atomicAdd(&g_counts[i], v);
    }
}

__global__ void k_scan() {  // 1 block, 512 threads
    __shared__ int s[NN];
    int t = threadIdx.x;
    int my = g_counts[t];
    s[t] = my;
    __syncthreads();
    #pragma unroll
    for (int off = 1; off < NN; off <<= 1) {
        int v = (t >= off) ? s[t - off] : 0;
        __syncthreads();
        s[t] += v;
        __syncthreads();
    }
    if (t == 0) g_offsets[0] = 0;
    g_offsets[t + 1] = s[t];
    g_cursor[t] = s[t] - my;  // exclusive prefix
}

__global__ void k_scatter(const int* __restrict__ ei,
                          const float4* __restrict__ ea) {
    int e = blockIdx.x * blockDim.x + threadIdx.x;
    if (e >= NE) return;
    int s = ei[e] & NMASK;
    int d = ei[NE + e] & NMASK;
    int p = atomicAdd(&g_cursor[d], 1);
    g_src[p] = s;
    g_ea[p]  = ea[e];
}

// ---------------- layer 1: cin=1, cout=36 ----------------
__global__ __launch_bounds__(128) void k_layer1(
    const float* __restrict__ x, const float* __restrict__ w,
    const float* __restrict__ b, const float* __restrict__ root,
    const float* __restrict__ bias)
{
    __shared__ float sW[4 * 36];
    __shared__ float sB[36];
    __shared__ float sAgg[36];
    int n = blockIdx.x, t = threadIdx.x;
    for (int i = t; i < 144; i += blockDim.x) sW[i] = w[i];
    if (t < 36) { sB[t] = b[t]; sAgg[t] = 0.f; }
    __syncthreads();

    int e0 = g_offsets[n], e1 = g_offsets[n + 1];
    float acc[36];
    #pragma unroll
    for (int o = 0; o < 36; o++) acc[o] = 0.f;

    for (int p = e0 + t; p < e1; p += blockDim.x) {
        float4 a = g_ea[p];
        float xs = x[g_src[p]];
        #pragma unroll
        for (int o = 0; o < 36; o++) {
            float z = sB[o];
            z = fmaf(a.x, sW[o], z);
            z = fmaf(a.y, sW[36 + o], z);
            z = fmaf(a.z, sW[72 + o], z);
            z = fmaf(a.w, sW[108 + o], z);
            acc[o] = fmaf(xs, fmaxf(z, 0.f), acc[o]);
        }
    }
    #pragma unroll
    for (int o = 0; o < 36; o++) {
        float v = acc[o];
        #pragma unroll
        for (int sh = 16; sh; sh >>= 1) v += __shfl_down_sync(0xFFFFFFFFu, v, sh);
        if ((t & 31) == 0) atomicAdd(&sAgg[o], v);
    }
    __syncthreads();
    if (t < 36) {
        float cnt = fmaxf((float)(e1 - e0), 1.f);
        float hv = sAgg[t] / cnt + x[n] * root[t] + bias[t];
        g_h1[n * 36 + t] = fmaxf(hv, 0.f);
    }
}

// ---------------- layer 2: cin=36, cout=24 (heavy; packed f32x2, 2 edges/thread) ----------------
__global__ __launch_bounds__(256) void k_layer2(
    const float* __restrict__ w, const float* __restrict__ b,
    const float* __restrict__ root, const float* __restrict__ bias)
{
    __shared__ float2 sW2[4 * 864];  // [v][i][o], each weight duplicated (w,w)
    __shared__ float2 sB2[864];      // [i][o] duplicated
    __shared__ float  sR[36 * 24];
    __shared__ float  sAgg[24];
    int n = blockIdx.x, t = threadIdx.x;
    for (int i = t; i < 3456; i += 256) { float v = w[i]; sW2[i] = make_float2(v, v); }
    for (int i = t; i < 864; i += 256)  { float v = b[i]; sB2[i] = make_float2(v, v); }
    for (int i = t; i < 864; i += 256)  sR[i] = root[i];
    if (t < 24) sAgg[t] = 0.f;
    __syncthreads();

    // float4 view: one float4 = two duplicated pairs = two adjacent o channels
    const float4* B4  = (const float4*)sB2;          // [i*12 + q]
    const float4* W40 = (const float4*)(sW2);        // v=0
    const float4* W41 = (const float4*)(sW2 + 864);  // v=1
    const float4* W42 = (const float4*)(sW2 + 1728); // v=2
    const float4* W43 = (const float4*)(sW2 + 2592); // v=3

    int e0 = g_offsets[n], e1 = g_offsets[n + 1];
    float2 acc[24];
    #pragma unroll
    for (int o = 0; o < 24; o++) acc[o] = make_float2(0.f, 0.f);

    for (int p = e0 + 2 * t; p < e1; p += 512) {
        bool has1 = (p + 1 < e1);
        float4 a0 = g_ea[p];
        int   s0 = g_src[p];
        float4 a1 = has1 ? g_ea[p + 1] : make_float4(0.f, 0.f, 0.f, 0.f);
        int   s1 = has1 ? g_src[p + 1] : s0;
        const float4* h0r = (const float4*)&g_h1[s0 * 36];
        const float4* h1r = (const float4*)&g_h1[s1 * 36];
        float2 ap0 = make_float2(a0.x, a1.x);
        float2 ap1 = make_float2(a0.y, a1.y);
        float2 ap2 = make_float2(a0.z, a1.z);
        float2 ap3 = make_float2(a0.w, a1.w);

        #pragma unroll
        for (int qh = 0; qh < 9; qh++) {
            float4 h0v = h0r[qh];
            float4 h1v = h1r[qh];
            if (!has1) h1v = make_float4(0.f, 0.f, 0.f, 0.f);  // phantom edge: h=0 kills its term
            float2 hp[4] = { make_float2(h0v.x, h1v.x), make_float2(h0v.y, h1v.y),
                             make_float2(h0v.z, h1v.z), make_float2(h0v.w, h1v.w) };
            #pragma unroll
            for (int ii = 0; ii < 4; ii++) {
                int i = qh * 4 + ii;
                float2 hi = hp[ii];
                #pragma unroll
                for (int q = 0; q < 12; q++) {   // 12 chunks x 2 o-channels
                    int idx = i * 12 + q;
                    float4 bz = B4[idx];
                    float2 z0 = make_float2(bz.x, bz.y);
                    float2 z1 = make_float2(bz.z, bz.w);
                    float4 w0 = W40[idx];
                    z0 = ffma2(ap0, make_float2(w0.x, w0.y), z0);
                    z1 = ffma2(ap0, make_float2(w0.z, w0.w), z1);
                    float4 w1 = W41[idx];
                    z0 = ffma2(ap1, make_float2(w1.x, w1.y), z0);
                    z1 = ffma2(ap1, make_float2(w1.z, w1.w), z1);
                    float4 w2 = W42[idx];
                    z0 = ffma2(ap2, make_float2(w2.x, w2.y), z0);
                    z1 = ffma2(ap2, make_float2(w2.z, w2.w), z1);
                    float4 w3 = W43[idx];
                    z0 = ffma2(ap3, make_float2(w3.x, w3.y), z0);
                    z1 = ffma2(ap3, make_float2(w3.z, w3.w), z1);
                    z0.x = fmaxf(z0.x, 0.f); z0.y = fmaxf(z0.y, 0.f);
                    z1.x = fmaxf(z1.x, 0.f); z1.y = fmaxf(z1.y, 0.f);
                    acc[2 * q]     = ffma2(hi, z0, acc[2 * q]);
                    acc[2 * q + 1] = ffma2(hi, z1, acc[2 * q + 1]);
                }
            }
        }
    }
    #pragma unroll
    for (int o = 0; o < 24; o++) {
        float v = acc[o].x + acc[o].y;
        #pragma unroll
        for (int sh = 16; sh; sh >>= 1) v += __shfl_down_sync(0xFFFFFFFFu, v, sh);
        if ((t & 31) == 0) atomicAdd(&sAgg[o], v);
    }
    __syncthreads();
    if (t < 24) {
        float cnt = fmaxf((float)(e1 - e0), 1.f);
        float r = sAgg[t] / cnt + bias[t];
        #pragma unroll
        for (int i = 0; i < 36; i++) r = fmaf(g_h1[n * 36 + i], sR[i * 24 + t], r);
        g_h2[n * 24 + t] = fmaxf(r, 0.f);
    }
}

// ---------------- layer 3: cin=24, cout=8 ----------------
__global__ __launch_bounds__(256) void k_layer3(
    const float* __restrict__ w, const float* __restrict__ b,
    const float* __restrict__ root, const float* __restrict__ bias)
{
    __shared__ float sW[4 * 192];   // [v][i][o]
    __shared__ float sB[192];
    __shared__ float sR[24 * 8];
    __shared__ float sAgg[8];
    int n = blockIdx.x, t = threadIdx.x;
    for (int i = t; i < 768; i += 256) sW[i] = w[i];
    for (int i = t; i < 192; i += 256) { sB[i] = b[i]; sR[i] = root[i]; }
    if (t < 8) sAgg[t] = 0.f;
    __syncthreads();

    const float4* W4 = (const float4*)sW;   // stride per v = 48
    const float4* B4 = (const float4*)sB;

    int e0 = g_offsets[n], e1 = g_offsets[n + 1];
    float acc[8];
    #pragma unroll
    for (int o = 0; o < 8; o++) acc[o] = 0.f;

    for (int p = e0 + t; p < e1; p += 256) {
        float4 a = g_ea[p];
        int s = g_src[p];
        const float4* hrow = (const float4*)&g_h2[s * 24];
        #pragma unroll
        for (int qh = 0; qh < 6; qh++) {
            float4 hv = hrow[qh];
            float hvals[4] = {hv.x, hv.y, hv.z, hv.w};
            #pragma unroll
            for (int ii = 0; ii < 4; ii++) {
                int i = qh * 4 + ii;
                float hi = hvals[ii];
                #pragma unroll
                for (int q = 0; q < 2; q++) {
                    int idx = i * 2 + q;
                    float4 bz = B4[idx];
                    float4 w0 = W4[idx];
                    float4 w1 = W4[48 + idx];
                    float4 w2 = W4[96 + idx];
                    float4 w3 = W4[144 + idx];
                    float z0 = fmaf(a.x, w0.x, fmaf(a.y, w1.x, fmaf(a.z, w2.x, fmaf(a.w, w3.x, bz.x))));
                    float z1 = fmaf(a.x, w0.y, fmaf(a.y, w1.y, fmaf(a.z, w2.y, fmaf(a.w, w3.y, bz.y))));
                    float z2 = fmaf(a.x, w0.z, fmaf(a.y, w1.z, fmaf(a.z, w2.z, fmaf(a.w, w3.z, bz.z))));
                    float z3 = fmaf(a.x, w0.w, fmaf(a.y, w1.w, fmaf(a.z, w2.w, fmaf(a.w, w3.w, bz.w))));
                    acc[q * 4 + 0] = fmaf(hi, fmaxf(z0, 0.f), acc[q * 4 + 0]);
                    acc[q * 4 + 1] = fmaf(hi, fmaxf(z1, 0.f), acc[q * 4 + 1]);
                    acc[q * 4 + 2] = fmaf(hi, fmaxf(z2, 0.f), acc[q * 4 + 2]);
                    acc[q * 4 + 3] = fmaf(hi, fmaxf(z3, 0.f), acc[q * 4 + 3]);
                }
            }
        }
    }
    #pragma unroll
    for (int o = 0; o < 8; o++) {
        float v = acc[o];
        #pragma unroll
        for (int sh = 16; sh; sh >>= 1) v += __shfl_down_sync(0xFFFFFFFFu, v, sh);
        if ((t & 31) == 0) atomicAdd(&sAgg[o], v);
    }
    __syncthreads();
    if (t < 8) {
        float cnt = fmaxf((float)(e1 - e0), 1.f);
        float r = sAgg[t] / cnt + bias[t];
        #pragma unroll
        for (int i = 0; i < 24; i++) r = fmaf(g_h2[n * 24 + i], sR[i * 8 + t], r);
        g_h3[n * 8 + t] = fmaxf(r, 0.f);
    }
}

// ---------------- CBT: pairwise L1 over h3 [512, 8] ----------------
__global__ __launch_bounds__(256) void k_cbt(float* __restrict__ out) {
    int i = blockIdx.x;
    const float4* me = (const float4*)&g_h3[i * 8];
    float4 a0 = me[0], a1 = me[1];
    for (int j = threadIdx.x; j < NN; j += blockDim.x) {
        const float4* other = (const float4*)&g_h3[j * 8];
        float4 b0 = other[0], b1 = other[1];
        float s = fabsf(b0.x - a0.x) + fabsf(b0.y - a0.y) + fabsf(b0.z - a0.z) + fabsf(b0.w - a0.w)
                + fabsf(b1.x - a1.x) + fabsf(b1.y - a1.y) + fabsf(b1.z - a1.z) + fabsf(b1.w - a1.w);
        out[i * NN + j] = s;
    }
}

// ---------------- launch ----------------
extern "C" void kernel_launch(void* const* d_in, const int* in_sizes, int n_in,
                              void* d_out, int out_size) {
    const float* x   = (const float*)d_in[0];
    const float* ea  = (const float*)d_in[1];
    const int*   ei  = (const int*)d_in[2];
    const float *w1 = (const float*)d_in[3],  *b1 = (const float*)d_in[4];
    const float *r1 = (const float*)d_in[5],  *c1 = (const float*)d_in[6];
    const float *w2 = (const float*)d_in[7],  *b2 = (const float*)d_in[8];
    const float *r2 = (const float*)d_in[9],  *c2 = (const float*)d_in[10];
    const float *w3 = (const float*)d_in[11], *b3 = (const float*)d_in[12];
    const float *r3 = (const float*)d_in[13], *c3 = (const float*)d_in[14];
    float* out = (float*)d_out;

    k_zero_counts<<<1, 512>>>();
    k_hist<<<148, 256>>>(ei);
    k_scan<<<1, 512>>>();
    k_scatter<<<NE / 256, 256>>>(ei, (const float4*)ea);

    k_layer1<<<NN, 128>>>(x, w1, b1, r1, c1);
    k_layer2<<<NN, 256>>>(w2, b2, r2, c2);
    k_layer3<<<NN, 256>>>(w3, b3, r3, c3);
    k_cbt<<<NN, 256>>>(out);
}

// round 5
// speedup vs baseline: 2.4677x; 2.4677x over previous
#include <cuda_runtime.h>
#include <cuda_bf16.h>

#define NN 512
#define NE (512*512)
#define NMASK (NN - 1)

// ---------------- scratch (static device globals; no allocation) ----------------
__device__ int    g_counts[NN];
__device__ int    g_offsets[NN + 1];
__device__ int    g_cursor[NN];
__device__ int    g_done;
__device__ int    g_src[NE];
__device__ float4 g_ea[NE];
__device__ float  g_h1[NN * 36];
__device__ float  g_h2[NN * 24];
__device__ float  g_h3[NN * 8];

// ---------------- fused histogram + last-block scan ----------------
// Replay-safe: g_counts and g_done are zero on entry (zero-initialized at load,
// and the elected block re-zeros them at the end of every run).
__global__ __launch_bounds__(512) void k_hist_scan(const int* __restrict__ ei) {
    __shared__ int sc[NN];
    __shared__ int s_flag;
    int t = threadIdx.x;
    sc[t] = 0;
    __syncthreads();
    for (int e = blockIdx.x * blockDim.x + t; e < NE; e += gridDim.x * blockDim.x) {
        int d = ei[NE + e] & NMASK;
        atomicAdd(&sc[d], 1);
    }
    __syncthreads();
    {
        int v = sc[t];
        if (v) atomicAdd(&g_counts[t], v);
    }
    __threadfence();
    __syncthreads();
    if (t == 0) {
        int prev = atomicAdd(&g_done, 1);
        s_flag = (prev == (int)gridDim.x - 1) ? 1 : 0;
    }
    __syncthreads();
    if (!s_flag) return;

    // elected last block: scan 512 bins
    __threadfence();
    int my = atomicAdd(&g_counts[t], 0);   // L1-bypassing read of final counts
    sc[t] = my;
    __syncthreads();
    #pragma unroll
    for (int off = 1; off < NN; off <<= 1) {
        int v = (t >= off) ? sc[t - off] : 0;
        __syncthreads();
        sc[t] += v;
        __syncthreads();
    }
    if (t == 0) { g_offsets[0] = 0; g_done = 0; }
    g_offsets[t + 1] = sc[t];
    g_cursor[t] = sc[t] - my;   // exclusive prefix
    g_counts[t] = 0;            // reset for next replay
}

__global__ void k_scatter(const int* __restrict__ ei,
                          const float4* __restrict__ ea) {
    int e = blockIdx.x * blockDim.x + threadIdx.x;
    if (e >= NE) return;
    int s = ei[e] & NMASK;
    int d = ei[NE + e] & NMASK;
    int p = atomicAdd(&g_cursor[d], 1);
    g_src[p] = s;
    g_ea[p]  = ea[e];
}

// ---------------- layer 1: cin=1, cout=36 ----------------
__global__ __launch_bounds__(128) void k_layer1(
    const float* __restrict__ x, const float* __restrict__ w,
    const float* __restrict__ b, const float* __restrict__ root,
    const float* __restrict__ bias)
{
    __shared__ float sW[4 * 36];
    __shared__ float sB[36];
    __shared__ float sAgg[36];
    int n = blockIdx.x, t = threadIdx.x;
    for (int i = t; i < 144; i += blockDim.x) sW[i] = w[i];
    if (t < 36) { sB[t] = b[t]; sAgg[t] = 0.f; }
    __syncthreads();

    int e0 = g_offsets[n], e1 = g_offsets[n + 1];
    float acc[36];
    #pragma unroll
    for (int o = 0; o < 36; o++) acc[o] = 0.f;

    for (int p = e0 + t; p < e1; p += blockDim.x) {
        float4 a = g_ea[p];
        float xs = x[g_src[p]];
        #pragma unroll
        for (int o = 0; o < 36; o++) {
            float z = sB[o];
            z = fmaf(a.x, sW[o], z);
            z = fmaf(a.y, sW[36 + o], z);
            z = fmaf(a.z, sW[72 + o], z);
            z = fmaf(a.w, sW[108 + o], z);
            acc[o] = fmaf(xs, fmaxf(z, 0.f), acc[o]);
        }
    }
    #pragma unroll
    for (int o = 0; o < 36; o++) {
        float v = acc[o];
        #pragma unroll
        for (int sh = 16; sh; sh >>= 1) v += __shfl_down_sync(0xFFFFFFFFu, v, sh);
        if ((t & 31) == 0) atomicAdd(&sAgg[o], v);
    }
    __syncthreads();
    if (t < 36) {
        float cnt = fmaxf((float)(e1 - e0), 1.f);
        float hv = sAgg[t] / cnt + x[n] * root[t] + bias[t];
        g_h1[n * 36 + t] = fmaxf(hv, 0.f);
    }
}

// ---------------- layer 2: cin=36, cout=24 (scalar, bounded unroll) ----------------
__global__ __launch_bounds__(256) void k_layer2(
    const float* __restrict__ w, const float* __restrict__ b,
    const float* __restrict__ root, const float* __restrict__ bias)
{
    __shared__ float sW[4 * 864];   // [v][i][o]
    __shared__ float sB[864];       // [i][o]
    __shared__ float sR[36 * 24];
    __shared__ float sAgg[24];
    int n = blockIdx.x, t = threadIdx.x;
    for (int i = t; i < 3456; i += 256) sW[i] = w[i];
    for (int i = t; i < 864; i += 256) sB[i] = b[i];
    for (int i = t; i < 864; i += 256) sR[i] = root[i];
    if (t < 24) sAgg[t] = 0.f;
    __syncthreads();

    const float4* W4 = (const float4*)sW;   // stride per v = 216 float4
    const float4* B4 = (const float4*)sB;

    int e0 = g_offsets[n], e1 = g_offsets[n + 1];
    float acc[24];
    #pragma unroll
    for (int o = 0; o < 24; o++) acc[o] = 0.f;

    for (int p = e0 + t; p < e1; p += 256) {
        float4 a = g_ea[p];
        int s = g_src[p];
        const float4* hrow = (const float4*)&g_h1[s * 36];
        #pragma unroll 1
        for (int qh = 0; qh < 9; qh++) {
            float4 hv = hrow[qh];
            float hvals[4] = {hv.x, hv.y, hv.z, hv.w};
            #pragma unroll
            for (int ii = 0; ii < 4; ii++) {
                int i = qh * 4 + ii;
                float hi = hvals[ii];
                #pragma unroll
                for (int q = 0; q < 6; q++) {
                    int idx = i * 6 + q;
                    float4 bz = B4[idx];
                    float4 w0 = W4[idx];
                    float4 w1 = W4[216 + idx];
                    float4 w2 = W4[432 + idx];
                    float4 w3 = W4[648 + idx];
                    float z0 = fmaf(a.x, w0.x, fmaf(a.y, w1.x, fmaf(a.z, w2.x, fmaf(a.w, w3.x, bz.x))));
                    float z1 = fmaf(a.x, w0.y, fmaf(a.y, w1.y, fmaf(a.z, w2.y, fmaf(a.w, w3.y, bz.y))));
                    float z2 = fmaf(a.x, w0.z, fmaf(a.y, w1.z, fmaf(a.z, w2.z, fmaf(a.w, w3.z, bz.z))));
                    float z3 = fmaf(a.x, w0.w, fmaf(a.y, w1.w, fmaf(a.z, w2.w, fmaf(a.w, w3.w, bz.w))));
                    acc[q * 4 + 0] = fmaf(hi, fmaxf(z0, 0.f), acc[q * 4 + 0]);
                    acc[q * 4 + 1] = fmaf(hi, fmaxf(z1, 0.f), acc[q * 4 + 1]);
                    acc[q * 4 + 2] = fmaf(hi, fmaxf(z2, 0.f), acc[q * 4 + 2]);
                    acc[q * 4 + 3] = fmaf(hi, fmaxf(z3, 0.f), acc[q * 4 + 3]);
                }
            }
        }
    }
    #pragma unroll
    for (int o = 0; o < 24; o++) {
        float v = acc[o];
        #pragma unroll
        for (int sh = 16; sh; sh >>= 1) v += __shfl_down_sync(0xFFFFFFFFu, v, sh);
        if ((t & 31) == 0) atomicAdd(&sAgg[o], v);
    }
    __syncthreads();
    if (t < 24) {
        float cnt = fmaxf((float)(e1 - e0), 1.f);
        float r = sAgg[t] / cnt + bias[t];
        #pragma unroll
        for (int i = 0; i < 36; i++) r = fmaf(g_h1[n * 36 + i], sR[i * 24 + t], r);
        g_h2[n * 24 + t] = fmaxf(r, 0.f);
    }
}

// ---------------- layer 3: cin=24, cout=8 ----------------
__global__ __launch_bounds__(256) void k_layer3(
    const float* __restrict__ w, const float* __restrict__ b,
    const float* __restrict__ root, const float* __restrict__ bias)
{
    __shared__ float sW[4 * 192];   // [v][i][o]
    __shared__ float sB[192];
    __shared__ float sR[24 * 8];
    __shared__ float sAgg[8];
    int n = blockIdx.x, t = threadIdx.x;
    for (int i = t; i < 768; i += 256) sW[i] = w[i];
    for (int i = t; i < 192; i += 256) { sB[i] = b[i]; sR[i] = root[i]; }
    if (t < 8) sAgg[t] = 0.f;
    __syncthreads();

    const float4* W4 = (const float4*)sW;   // stride per v = 48 float4
    const float4* B4 = (const float4*)sB;

    int e0 = g_offsets[n], e1 = g_offsets[n + 1];
    float acc[8];
    #pragma unroll
    for (int o = 0; o < 8; o++) acc[o] = 0.f;

    for (int p = e0 + t; p < e1; p += 256) {
        float4 a = g_ea[p];
        int s = g_src[p];
        const float4* hrow = (const float4*)&g_h2[s * 24];
        #pragma unroll 1
        for (int qh = 0; qh < 6; qh++) {
            float4 hv = hrow[qh];
            float hvals[4] = {hv.x, hv.y, hv.z, hv.w};
            #pragma unroll
            for (int ii = 0; ii < 4; ii++) {
                int i = qh * 4 + ii;
                float hi = hvals[ii];
                #pragma unroll
                for (int q = 0; q < 2; q++) {
                    int idx = i * 2 + q;
                    float4 bz = B4[idx];
                    float4 w0 = W4[idx];
                    float4 w1 = W4[48 + idx];
                    float4 w2 = W4[96 + idx];
                    float4 w3 = W4[144 + idx];
                    float z0 = fmaf(a.x, w0.x, fmaf(a.y, w1.x, fmaf(a.z, w2.x, fmaf(a.w, w3.x, bz.x))));
                    float z1 = fmaf(a.x, w0.y, fmaf(a.y, w1.y, fmaf(a.z, w2.y, fmaf(a.w, w3.y, bz.y))));
                    float z2 = fmaf(a.x, w0.z, fmaf(a.y, w1.z, fmaf(a.z, w2.z, fmaf(a.w, w3.z, bz.z))));
                    float z3 = fmaf(a.x, w0.w, fmaf(a.y, w1.w, fmaf(a.z, w2.w, fmaf(a.w, w3.w, bz.w))));
                    acc[q * 4 + 0] = fmaf(hi, fmaxf(z0, 0.f), acc[q * 4 + 0]);
                    acc[q * 4 + 1] = fmaf(hi, fmaxf(z1, 0.f), acc[q * 4 + 1]);
                    acc[q * 4 + 2] = fmaf(hi, fmaxf(z2, 0.f), acc[q * 4 + 2]);
                    acc[q * 4 + 3] = fmaf(hi, fmaxf(z3, 0.f), acc[q * 4 + 3]);
                }
            }
        }
    }
    #pragma unroll
    for (int o = 0; o < 8; o++) {
        float v = acc[o];
        #pragma unroll
        for (int sh = 16; sh; sh >>= 1) v += __shfl_down_sync(0xFFFFFFFFu, v, sh);
        if ((t & 31) == 0) atomicAdd(&sAgg[o], v);
    }
    __syncthreads();
    if (t < 8) {
        float cnt = fmaxf((float)(e1 - e0), 1.f);
        float r = sAgg[t] / cnt + bias[t];
        #pragma unroll
        for (int i = 0; i < 24; i++) r = fmaf(g_h2[n * 24 + i], sR[i * 8 + t], r);
        g_h3[n * 8 + t] = fmaxf(r, 0.f);
    }
}

// ---------------- CBT: pairwise L1 over h3 [512, 8] ----------------
__global__ __launch_bounds__(256) void k_cbt(float* __restrict__ out) {
    int i = blockIdx.x;
    const float4* me = (const float4*)&g_h3[i * 8];
    float4 a0 = me[0], a1 = me[1];
    for (int j = threadIdx.x; j < NN; j += blockDim.x) {
        const float4* other = (const float4*)&g_h3[j * 8];
        float4 b0 = other[0], b1 = other[1];
        float s = fabsf(b0.x - a0.x) + fabsf(b0.y - a0.y) + fabsf(b0.z - a0.z) + fabsf(b0.w - a0.w)
                + fabsf(b1.x - a1.x) + fabsf(b1.y - a1.y) + fabsf(b1.z - a1.z) + fabsf(b1.w - a1.w);
        out[i * NN + j] = s;
    }
}

// ---------------- launch ----------------
extern "C" void kernel_launch(void* const* d_in, const int* in_sizes, int n_in,
                              void* d_out, int out_size) {
    const float* x   = (const float*)d_in[0];
    const float* ea  = (const float*)d_in[1];
    const int*   ei  = (const int*)d_in[2];
    const float *w1 = (const float*)d_in[3],  *b1 = (const float*)d_in[4];
    const float *r1 = (const float*)d_in[5],  *c1 = (const float*)d_in[6];
    const float *w2 = (const float*)d_in[7],  *b2 = (const float*)d_in[8];
    const float *r2 = (const float*)d_in[9],  *c2 = (const float*)d_in[10];
    const float *w3 = (const float*)d_in[11], *b3 = (const float*)d_in[12];
    const float *r3 = (const float*)d_in[13], *c3 = (const float*)d_in[14];
    float* out = (float*)d_out;

    k_hist_scan<<<148, 512>>>(ei);
    k_scatter<<<NE / 256, 256>>>(ei, (const float4*)ea);

    k_layer1<<<NN, 128>>>(x, w1, b1, r1, c1);
    k_layer2<<<NN, 256>>>(w2, b2, r2, c2);   // 6th launch overall -> ncu capture target
    k_layer3<<<NN, 256>>>(w3, b3, r3, c3);
    k_cbt<<<NN, 256>>>(out);
}